// round 4
// baseline (speedup 1.0000x reference)
#include <cuda_runtime.h>

// Problem constants
#define BB 4
#define SS 4096
#define MD 1024
#define HD 128
#define NROWS (BB*SS)      // 16384
#define NCOL  384          // 3 weights * 128

// Attention tiling
#define QT 128
#define KT 64
#define PQ 132             // pitch (floats) for Q/K/V smem tiles
#define PP 68              // pitch (floats) for P tile
#define NQT (SS/QT)        // 32
#define ATT_THREADS 256
#define SMEM_FLOATS (QT*PQ + 2*KT*PQ + QT*PP)   // 42496 floats = 169984 B

// Scratch (device globals; no allocations allowed)
__device__ float g_Wt[MD*NCOL];      // [m][w*128+h]
__device__ float g_K[NROWS*HD];
__device__ float g_Q[NROWS*HD];
__device__ float g_V[NROWS*HD];

// ---------------------------------------------------------------------------
// Kernel 0: transpose the three [H,M] weights into one [M, 3H] matrix
// ---------------------------------------------------------------------------
__global__ void transpose_w_kernel(const float* __restrict__ Wk,
                                   const float* __restrict__ Wq,
                                   const float* __restrict__ Wv) {
    int idx = blockIdx.x * blockDim.x + threadIdx.x;
    if (idx >= MD * NCOL) return;
    int m = idx / NCOL;
    int c = idx - m * NCOL;
    int w = c >> 7;
    int h = c & 127;
    const float* src = (w == 0) ? Wk : (w == 1) ? Wq : Wv;
    g_Wt[idx] = src[h * MD + m];
}

// ---------------------------------------------------------------------------
// Kernel 1: QKV projection GEMM  C[16384,384] = E[16384,1024] * Wt[1024,384]
// Block tile 128x128x8, 256 threads, 8x8 register microtile.
// blockIdx.y selects which of K/Q/V this 128-column group is.
// ---------------------------------------------------------------------------
__global__ __launch_bounds__(256) void qkv_gemm_kernel(const float* __restrict__ A) {
    __shared__ float As[8][132];   // transposed A tile: As[k][row]
    __shared__ float Bs[8][132];   // Bs[k][col]

    const int tid = threadIdx.x;
    const int tx  = tid & 15;
    const int ty  = tid >> 4;
    const int rowBase = blockIdx.x * 128;
    const int c0      = blockIdx.y * 128;

    float acc[8][8];
    #pragma unroll
    for (int i = 0; i < 8; i++)
        #pragma unroll
        for (int j = 0; j < 8; j++) acc[i][j] = 0.f;

    const int lr = tid >> 1;          // A tile row this thread loads
    const int lh = (tid & 1) * 4;     // k offset within tile
    const int bk = tid >> 5;          // B tile k-row
    const int bc = (tid & 31) * 4;    // B tile col offset

    for (int k0 = 0; k0 < MD; k0 += 8) {
        float4 va = *(const float4*)&A[(size_t)(rowBase + lr) * MD + k0 + lh];
        float4 vb = *(const float4*)&g_Wt[(size_t)(k0 + bk) * NCOL + c0 + bc];
        __syncthreads();
        As[lh + 0][lr] = va.x;
        As[lh + 1][lr] = va.y;
        As[lh + 2][lr] = va.z;
        As[lh + 3][lr] = va.w;
        *(float4*)&Bs[bk][bc] = vb;
        __syncthreads();

        #pragma unroll
        for (int k = 0; k < 8; k++) {
            float4 a0 = *(const float4*)&As[k][ty * 4];
            float4 a1 = *(const float4*)&As[k][64 + ty * 4];
            float4 b0 = *(const float4*)&Bs[k][tx * 4];
            float4 b1 = *(const float4*)&Bs[k][64 + tx * 4];
            float a[8] = {a0.x, a0.y, a0.z, a0.w, a1.x, a1.y, a1.z, a1.w};
            float b[8] = {b0.x, b0.y, b0.z, b0.w, b1.x, b1.y, b1.z, b1.w};
            #pragma unroll
            for (int i = 0; i < 8; i++)
                #pragma unroll
                for (int j = 0; j < 8; j++)
                    acc[i][j] += a[i] * b[j];
        }
    }

    float* outp = (blockIdx.y == 0) ? g_K : (blockIdx.y == 1) ? g_Q : g_V;
    #pragma unroll
    for (int i = 0; i < 8; i++) {
        int row = rowBase + ((i < 4) ? (ty * 4 + i) : (64 + ty * 4 + i - 4));
        float4 v0 = make_float4(acc[i][0], acc[i][1], acc[i][2], acc[i][3]);
        float4 v1 = make_float4(acc[i][4], acc[i][5], acc[i][6], acc[i][7]);
        *(float4*)&outp[(size_t)row * HD + tx * 4]      = v0;
        *(float4*)&outp[(size_t)row * HD + 64 + tx * 4] = v1;
    }
}

// ---------------------------------------------------------------------------
// Kernel 2: causal flash attention, fp32, online softmax.
// Grid: 128 blocks = 4 batches x 32 q-tiles (heavy diagonal tiles first).
// 256 threads: tx = tid&7 (8 k/d lanes), ty = tid>>3 (32 row groups of 4).
// S microtile: 4 q-rows x 8 k-cols (cols interleaved tx+8j -> bank-clean).
// O microtile: 4 q-rows x 16 d   (d interleaved 4tx+32jj -> bank-clean).
// ---------------------------------------------------------------------------
__global__ __launch_bounds__(ATT_THREADS, 1) void attn_kernel(float* __restrict__ Out) {
    extern __shared__ float sm[];
    float* Qs = sm;                  // [QT][PQ]
    float* Ks = Qs + QT * PQ;        // [KT][PQ]
    float* Vs = Ks + KT * PQ;        // [KT][PQ]
    float* Ps = Vs + KT * PQ;        // [QT][PP]

    const int bid   = blockIdx.x;
    const int qt    = (NQT - 1) - (bid >> 2);   // heavy tiles first
    const int b     = bid & 3;
    const int qbase = qt * QT;

    const float* Qg = g_Q + (size_t)b * SS * HD;
    const float* Kg = g_K + (size_t)b * SS * HD;
    const float* Vg = g_V + (size_t)b * SS * HD;

    const int tid = threadIdx.x;
    const int tx  = tid & 7;
    const int ty  = tid >> 3;
    const int r0  = ty * 4;

    const float scale = 0.08838834764831845f;   // 1/sqrt(128)

    // Load Q tile (pre-scaled)
    for (int i = tid; i < QT * (HD / 4); i += ATT_THREADS) {
        int row = i >> 5;
        int dq  = (i & 31) << 2;
        float4 v = *(const float4*)&Qg[(size_t)(qbase + row) * HD + dq];
        v.x *= scale; v.y *= scale; v.z *= scale; v.w *= scale;
        *(float4*)&Qs[row * PQ + dq] = v;
    }

    float o[4][16];
    #pragma unroll
    for (int i = 0; i < 4; i++)
        #pragma unroll
        for (int j = 0; j < 16; j++) o[i][j] = 0.f;
    float mr[4] = {-1e30f, -1e30f, -1e30f, -1e30f};
    float lr[4] = {0.f, 0.f, 0.f, 0.f};

    const int nkt = (qbase + QT) / KT;          // tiles up to & incl. diagonal band
    for (int kt = 0; kt < nkt; kt++) {
        const int kbase = kt * KT;
        __syncthreads();   // prior iteration done reading Ks/Vs/Ps (and covers Qs init)
        for (int i = tid; i < KT * (HD / 4); i += ATT_THREADS) {
            int row = i >> 5;
            int dq  = (i & 31) << 2;
            *(float4*)&Ks[row * PQ + dq] = *(const float4*)&Kg[(size_t)(kbase + row) * HD + dq];
            *(float4*)&Vs[row * PQ + dq] = *(const float4*)&Vg[(size_t)(kbase + row) * HD + dq];
        }
        __syncthreads();

        // ---- S = (Q*scale) @ K^T : 4x8 per thread ----
        float s[4][8];
        #pragma unroll
        for (int i = 0; i < 4; i++)
            #pragma unroll
            for (int j = 0; j < 8; j++) s[i][j] = 0.f;

        #pragma unroll 2
        for (int d = 0; d < HD; d += 4) {
            float4 q[4];
            #pragma unroll
            for (int i = 0; i < 4; i++) q[i] = *(const float4*)&Qs[(r0 + i) * PQ + d];
            #pragma unroll
            for (int j = 0; j < 8; j++) {
                float4 kv = *(const float4*)&Ks[(tx + 8 * j) * PQ + d];
                #pragma unroll
                for (int i = 0; i < 4; i++) {
                    s[i][j] += q[i].x * kv.x;
                    s[i][j] += q[i].y * kv.y;
                    s[i][j] += q[i].z * kv.z;
                    s[i][j] += q[i].w * kv.w;
                }
            }
        }

        // ---- causal mask + online softmax (row reduce over tx via shuffles) ----
        const bool needMask = (kbase + KT - 1 > qbase);
        #pragma unroll
        for (int i = 0; i < 4; i++) {
            const int qg = qbase + r0 + i;
            if (needMask) {
                #pragma unroll
                for (int j = 0; j < 8; j++)
                    if (kbase + tx + 8 * j > qg) s[i][j] = -1e30f;
            }
            float mx = s[i][0];
            #pragma unroll
            for (int j = 1; j < 8; j++) mx = fmaxf(mx, s[i][j]);
            mx = fmaxf(mx, __shfl_xor_sync(0xffffffffu, mx, 1));
            mx = fmaxf(mx, __shfl_xor_sync(0xffffffffu, mx, 2));
            mx = fmaxf(mx, __shfl_xor_sync(0xffffffffu, mx, 4));
            float mnew  = fmaxf(mr[i], mx);
            float alpha = __expf(mr[i] - mnew);
            mr[i] = mnew;
            float ls = 0.f;
            #pragma unroll
            for (int j = 0; j < 8; j++) {
                float p = __expf(s[i][j] - mnew);
                s[i][j] = p;
                ls += p;
            }
            ls += __shfl_xor_sync(0xffffffffu, ls, 1);
            ls += __shfl_xor_sync(0xffffffffu, ls, 2);
            ls += __shfl_xor_sync(0xffffffffu, ls, 4);
            lr[i] = lr[i] * alpha + ls;
            #pragma unroll
            for (int d = 0; d < 16; d++) o[i][d] *= alpha;
            #pragma unroll
            for (int j = 0; j < 8; j++) Ps[(r0 + i) * PP + tx + 8 * j] = s[i][j];
        }
        __syncthreads();

        // ---- O += P @ V : 4 rows x 16 d per thread (d = 4*tx + 32*jj + q) ----
        #pragma unroll 2
        for (int kk = 0; kk < KT; kk++) {
            float p[4];
            #pragma unroll
            for (int i = 0; i < 4; i++) p[i] = Ps[(r0 + i) * PP + kk];
            #pragma unroll
            for (int jj = 0; jj < 4; jj++) {
                float4 v = *(const float4*)&Vs[kk * PQ + 4 * tx + 32 * jj];
                #pragma unroll
                for (int i = 0; i < 4; i++) {
                    o[i][jj * 4 + 0] += p[i] * v.x;
                    o[i][jj * 4 + 1] += p[i] * v.y;
                    o[i][jj * 4 + 2] += p[i] * v.z;
                    o[i][jj * 4 + 3] += p[i] * v.w;
                }
            }
        }
    }

    // ---- epilogue: normalize and store ----
    #pragma unroll
    for (int i = 0; i < 4; i++) {
        float inv = 1.0f / lr[i];
        size_t rowoff = (size_t)(b * SS + qbase + r0 + i) * HD;
        #pragma unroll
        for (int jj = 0; jj < 4; jj++) {
            float4 v = make_float4(o[i][jj * 4 + 0] * inv, o[i][jj * 4 + 1] * inv,
                                   o[i][jj * 4 + 2] * inv, o[i][jj * 4 + 3] * inv);
            *(float4*)&Out[rowoff + 4 * tx + 32 * jj] = v;
        }
    }
}

// ---------------------------------------------------------------------------
extern "C" void kernel_launch(void* const* d_in, const int* in_sizes, int n_in,
                              void* d_out, int out_size) {
    const float* E  = (const float*)d_in[0];
    const float* Wk = (const float*)d_in[1];
    const float* Wq = (const float*)d_in[2];
    const float* Wv = (const float*)d_in[3];
    float* Out = (float*)d_out;

    // Kernel 0: weight transpose
    transpose_w_kernel<<<(MD * NCOL + 255) / 256, 256>>>(Wk, Wq, Wv);

    // Kernel 1: QKV projection GEMM
    dim3 g1(NROWS / 128, 3);
    qkv_gemm_kernel<<<g1, 256>>>(E);

    // Kernel 2: causal flash attention
    size_t smem = (size_t)SMEM_FLOATS * sizeof(float);   // 169984 B
    cudaFuncSetAttribute(attn_kernel, cudaFuncAttributeMaxDynamicSharedMemorySize, (int)smem);
    attn_kernel<<<BB * NQT, ATT_THREADS, smem>>>(Out);
}

// round 6
// speedup vs baseline: 1.1616x; 1.1616x over previous
#include <cuda_runtime.h>
#include <cuda_bf16.h>
#include <cstdint>

// Problem constants
#define BB 4
#define SS 4096
#define MD 1024
#define HD 128
#define NROWS (BB*SS)      // 16384
#define NCOL  384

// Attention tiling (unchanged, verified fp32 kernel)
#define QT 128
#define KT 64
#define PQ 132
#define PP 68
#define NQT (SS/QT)
#define ATT_THREADS 256
#define SMEM_FLOATS (QT*PQ + 2*KT*PQ + QT*PP)

// HMMA GEMM tiling
#define KC 32                       // k elems per chunk
#define PITCHB 80                   // smem row pitch in bytes (40 bf16)
#define TILEB (128*PITCHB)          // 10240 B per operand tile
#define STAGEB (4*TILEB)            // Ahi,Alo,Bhi,Blo = 40960 B
#define GEMM_SMEM (2*STAGEB)        // 81920 B

// Scratch (device globals; no allocations allowed)
__device__ __nv_bfloat16 g_Ehi[NROWS*MD];
__device__ __nv_bfloat16 g_Elo[NROWS*MD];
__device__ __nv_bfloat16 g_Whi[NCOL*MD];   // rows 0-127=Wk, 128-255=Wq, 256-383=Wv
__device__ __nv_bfloat16 g_Wlo[NCOL*MD];
__device__ float g_K[NROWS*HD];
__device__ float g_Q[NROWS*HD];
__device__ float g_V[NROWS*HD];

// ---------------------------------------------------------------------------
// PTX helpers (base sm_103 target: mma.sync / ldmatrix / cp.async only)
// ---------------------------------------------------------------------------
__device__ __forceinline__ uint32_t smem_u32(const void* p) {
    uint32_t a;
    asm("{ .reg .u64 t; cvta.to.shared.u64 t, %1; cvt.u32.u64 %0, t; }" : "=r"(a) : "l"(p));
    return a;
}
__device__ __forceinline__ void ldsm4(uint32_t& r0, uint32_t& r1, uint32_t& r2, uint32_t& r3,
                                      uint32_t addr) {
    asm volatile("ldmatrix.sync.aligned.m8n8.x4.shared.b16 {%0,%1,%2,%3}, [%4];"
                 : "=r"(r0), "=r"(r1), "=r"(r2), "=r"(r3) : "r"(addr));
}
__device__ __forceinline__ void mma_bf16(float* c, const uint32_t* a, const uint32_t* b) {
    asm volatile(
        "mma.sync.aligned.m16n8k16.row.col.f32.bf16.bf16.f32 "
        "{%0,%1,%2,%3},{%4,%5,%6,%7},{%8,%9},{%0,%1,%2,%3};"
        : "+f"(c[0]), "+f"(c[1]), "+f"(c[2]), "+f"(c[3])
        : "r"(a[0]), "r"(a[1]), "r"(a[2]), "r"(a[3]), "r"(b[0]), "r"(b[1]));
}
__device__ __forceinline__ void cp_async16(uint32_t dst, const void* src) {
    asm volatile("cp.async.cg.shared.global [%0], [%1], 16;" :: "r"(dst), "l"(src));
}
__device__ __forceinline__ void cp_commit() {
    asm volatile("cp.async.commit_group;");
}
template <int N>
__device__ __forceinline__ void cp_wait() {
    asm volatile("cp.async.wait_group %0;" :: "n"(N));
}

// ---------------------------------------------------------------------------
// Kernel 0: fp32 -> split bf16 (hi + lo), hi = bf16(x), lo = bf16(x - hi)
// ---------------------------------------------------------------------------
__global__ void split_kernel(const float* __restrict__ src, int n4, int isE, long off) {
    int i = blockIdx.x * blockDim.x + threadIdx.x;
    if (i >= n4) return;
    float4 v = ((const float4*)src)[i];
    __nv_bfloat16 h0 = __float2bfloat16(v.x), h1 = __float2bfloat16(v.y);
    __nv_bfloat16 h2 = __float2bfloat16(v.z), h3 = __float2bfloat16(v.w);
    __nv_bfloat16 l0 = __float2bfloat16(v.x - __bfloat162float(h0));
    __nv_bfloat16 l1 = __float2bfloat16(v.y - __bfloat162float(h1));
    __nv_bfloat16 l2 = __float2bfloat16(v.z - __bfloat162float(h2));
    __nv_bfloat16 l3 = __float2bfloat16(v.w - __bfloat162float(h3));
    __nv_bfloat16* hi = (isE ? g_Ehi : g_Whi) + off;
    __nv_bfloat16* lo = (isE ? g_Elo : g_Wlo) + off;
    __nv_bfloat162 t;
    __nv_bfloat162* H = (__nv_bfloat162*)hi;
    __nv_bfloat162* L = (__nv_bfloat162*)lo;
    t.x = h0; t.y = h1; H[2 * i]     = t;
    t.x = h2; t.y = h3; H[2 * i + 1] = t;
    t.x = l0; t.y = l1; L[2 * i]     = t;
    t.x = l2; t.y = l3; L[2 * i + 1] = t;
}

// ---------------------------------------------------------------------------
// Kernel 1: split-bf16 HMMA QKV projection.
// C[128,128] per CTA; A = E rows (row-major [m][k]), B = W rows (col-major [n][k]).
// 8 warps in a 4x2 grid, warp tile 32x64, m16n8k16 fragments.
// ---------------------------------------------------------------------------
__global__ __launch_bounds__(256) void qkv_hmma_kernel() {
    extern __shared__ char sm_raw[];
    const uint32_t sb = smem_u32(sm_raw);

    const int tid  = threadIdx.x;
    const int warp = tid >> 5;
    const int lane = tid & 31;
    const int mbase = blockIdx.x * 128;
    const int c0    = blockIdx.y * 128;

    const int wr = (warp >> 1) * 32;   // warp row offset
    const int wc = (warp & 1) * 64;    // warp col offset

    // --- async loader: each 64-thread group fills one operand tile ---
    const int grp  = tid >> 6;         // 0:Ahi 1:Alo 2:Bhi 3:Blo
    const int lidx = tid & 63;
    const __nv_bfloat16* gsrc = (grp == 0) ? g_Ehi : (grp == 1) ? g_Elo
                              : (grp == 2) ? g_Whi : g_Wlo;
    const int growbase = (grp < 2) ? mbase : c0;

    auto issue_chunk = [&](int stage, int k0) {
        const uint32_t tb = sb + stage * STAGEB + grp * TILEB;
        #pragma unroll
        for (int it = 0; it < 8; it++) {
            const int idx = it * 64 + lidx;
            const int row = idx >> 2;
            const int c   = idx & 3;
            cp_async16(tb + row * PITCHB + c * 16,
                       gsrc + (size_t)(growbase + row) * MD + k0 + c * 8);
        }
        cp_commit();
    };

    float acc[2][8][4];
    #pragma unroll
    for (int m = 0; m < 2; m++)
        #pragma unroll
        for (int n = 0; n < 8; n++)
            #pragma unroll
            for (int j = 0; j < 4; j++) acc[m][n][j] = 0.f;

    issue_chunk(0, 0);
    issue_chunk(1, KC);

    // per-lane ldmatrix base offsets
    const uint32_t lrow16 = (uint32_t)(lane & 15);
    const uint32_t lcol16 = (uint32_t)(lane >> 4) * 16;

    const int NCHUNK = MD / KC;   // 32
    for (int chunk = 0; chunk < NCHUNK; chunk++) {
        const int stage = chunk & 1;
        cp_wait<1>();
        __syncthreads();

        const uint32_t Ah = sb + stage * STAGEB;
        const uint32_t Al = Ah + TILEB;
        const uint32_t Bh = Ah + 2 * TILEB;
        const uint32_t Bl = Ah + 3 * TILEB;

        #pragma unroll
        for (int kk = 0; kk < 2; kk++) {              // two k16 steps per chunk
            const uint32_t kb = kk * 32 + lcol16;     // byte offset along k

            uint32_t ah[2][4], al[2][4];
            #pragma unroll
            for (int m = 0; m < 2; m++) {
                const uint32_t ro = (wr + m * 16 + lrow16) * PITCHB + kb;
                ldsm4(ah[m][0], ah[m][1], ah[m][2], ah[m][3], Ah + ro);
                ldsm4(al[m][0], al[m][1], al[m][2], al[m][3], Al + ro);
            }
            uint32_t bh[8][2], bl[8][2];
            #pragma unroll
            for (int q = 0; q < 4; q++) {
                const uint32_t ro = (wc + q * 16 + lrow16) * PITCHB + kb;
                uint32_t r0, r1, r2, r3;
                ldsm4(r0, r1, r2, r3, Bh + ro);
                bh[q * 2][0] = r0; bh[q * 2][1] = r2;
                bh[q * 2 + 1][0] = r1; bh[q * 2 + 1][1] = r3;
                ldsm4(r0, r1, r2, r3, Bl + ro);
                bl[q * 2][0] = r0; bl[q * 2][1] = r2;
                bl[q * 2 + 1][0] = r1; bl[q * 2 + 1][1] = r3;
            }
            #pragma unroll
            for (int m = 0; m < 2; m++)
                #pragma unroll
                for (int n = 0; n < 8; n++) {
                    mma_bf16(acc[m][n], ah[m], bh[n]);
                    mma_bf16(acc[m][n], ah[m], bl[n]);
                    mma_bf16(acc[m][n], al[m], bh[n]);
                }
        }
        __syncthreads();
        if (chunk + 2 < NCHUNK) issue_chunk(stage, (chunk + 2) * KC);
    }

    // --- epilogue: fragment -> fp32 global ---
    float* outp = (blockIdx.y == 0) ? g_K : (blockIdx.y == 1) ? g_Q : g_V;
    const int qrow = lane >> 2;
    const int qcol = (lane & 3) * 2;
    #pragma unroll
    for (int m = 0; m < 2; m++) {
        const int r0g = mbase + wr + m * 16 + qrow;
        #pragma unroll
        for (int n = 0; n < 8; n++) {
            const int cg = wc + n * 8 + qcol;
            *(float2*)&outp[(size_t)r0g * HD + cg] =
                make_float2(acc[m][n][0], acc[m][n][1]);
            *(float2*)&outp[(size_t)(r0g + 8) * HD + cg] =
                make_float2(acc[m][n][2], acc[m][n][3]);
        }
    }
}

// ---------------------------------------------------------------------------
// Kernel 2: causal flash attention, fp32 (unchanged from passing baseline)
// ---------------------------------------------------------------------------
__global__ __launch_bounds__(ATT_THREADS, 1) void attn_kernel(float* __restrict__ Out) {
    extern __shared__ float sm[];
    float* Qs = sm;
    float* Ks = Qs + QT * PQ;
    float* Vs = Ks + KT * PQ;
    float* Ps = Vs + KT * PQ;

    const int bid   = blockIdx.x;
    const int qt    = (NQT - 1) - (bid >> 2);
    const int b     = bid & 3;
    const int qbase = qt * QT;

    const float* Qg = g_Q + (size_t)b * SS * HD;
    const float* Kg = g_K + (size_t)b * SS * HD;
    const float* Vg = g_V + (size_t)b * SS * HD;

    const int tid = threadIdx.x;
    const int tx  = tid & 7;
    const int ty  = tid >> 3;
    const int r0  = ty * 4;

    const float scale = 0.08838834764831845f;

    for (int i = tid; i < QT * (HD / 4); i += ATT_THREADS) {
        int row = i >> 5;
        int dq  = (i & 31) << 2;
        float4 v = *(const float4*)&Qg[(size_t)(qbase + row) * HD + dq];
        v.x *= scale; v.y *= scale; v.z *= scale; v.w *= scale;
        *(float4*)&Qs[row * PQ + dq] = v;
    }

    float o[4][16];
    #pragma unroll
    for (int i = 0; i < 4; i++)
        #pragma unroll
        for (int j = 0; j < 16; j++) o[i][j] = 0.f;
    float mr[4] = {-1e30f, -1e30f, -1e30f, -1e30f};
    float lr[4] = {0.f, 0.f, 0.f, 0.f};

    const int nkt = (qbase + QT) / KT;
    for (int kt = 0; kt < nkt; kt++) {
        const int kbase = kt * KT;
        __syncthreads();
        for (int i = tid; i < KT * (HD / 4); i += ATT_THREADS) {
            int row = i >> 5;
            int dq  = (i & 31) << 2;
            *(float4*)&Ks[row * PQ + dq] = *(const float4*)&Kg[(size_t)(kbase + row) * HD + dq];
            *(float4*)&Vs[row * PQ + dq] = *(const float4*)&Vg[(size_t)(kbase + row) * HD + dq];
        }
        __syncthreads();

        float s[4][8];
        #pragma unroll
        for (int i = 0; i < 4; i++)
            #pragma unroll
            for (int j = 0; j < 8; j++) s[i][j] = 0.f;

        #pragma unroll 2
        for (int d = 0; d < HD; d += 4) {
            float4 q[4];
            #pragma unroll
            for (int i = 0; i < 4; i++) q[i] = *(const float4*)&Qs[(r0 + i) * PQ + d];
            #pragma unroll
            for (int j = 0; j < 8; j++) {
                float4 kv = *(const float4*)&Ks[(tx + 8 * j) * PQ + d];
                #pragma unroll
                for (int i = 0; i < 4; i++) {
                    s[i][j] += q[i].x * kv.x;
                    s[i][j] += q[i].y * kv.y;
                    s[i][j] += q[i].z * kv.z;
                    s[i][j] += q[i].w * kv.w;
                }
            }
        }

        const bool needMask = (kbase + KT - 1 > qbase);
        #pragma unroll
        for (int i = 0; i < 4; i++) {
            const int qg = qbase + r0 + i;
            if (needMask) {
                #pragma unroll
                for (int j = 0; j < 8; j++)
                    if (kbase + tx + 8 * j > qg) s[i][j] = -1e30f;
            }
            float mx = s[i][0];
            #pragma unroll
            for (int j = 1; j < 8; j++) mx = fmaxf(mx, s[i][j]);
            mx = fmaxf(mx, __shfl_xor_sync(0xffffffffu, mx, 1));
            mx = fmaxf(mx, __shfl_xor_sync(0xffffffffu, mx, 2));
            mx = fmaxf(mx, __shfl_xor_sync(0xffffffffu, mx, 4));
            float mnew  = fmaxf(mr[i], mx);
            float alpha = __expf(mr[i] - mnew);
            mr[i] = mnew;
            float ls = 0.f;
            #pragma unroll
            for (int j = 0; j < 8; j++) {
                float p = __expf(s[i][j] - mnew);
                s[i][j] = p;
                ls += p;
            }
            ls += __shfl_xor_sync(0xffffffffu, ls, 1);
            ls += __shfl_xor_sync(0xffffffffu, ls, 2);
            ls += __shfl_xor_sync(0xffffffffu, ls, 4);
            lr[i] = lr[i] * alpha + ls;
            #pragma unroll
            for (int d = 0; d < 16; d++) o[i][d] *= alpha;
            #pragma unroll
            for (int j = 0; j < 8; j++) Ps[(r0 + i) * PP + tx + 8 * j] = s[i][j];
        }
        __syncthreads();

        #pragma unroll 2
        for (int kk = 0; kk < KT; kk++) {
            float p[4];
            #pragma unroll
            for (int i = 0; i < 4; i++) p[i] = Ps[(r0 + i) * PP + kk];
            #pragma unroll
            for (int jj = 0; jj < 4; jj++) {
                float4 v = *(const float4*)&Vs[kk * PQ + 4 * tx + 32 * jj];
                #pragma unroll
                for (int i = 0; i < 4; i++) {
                    o[i][jj * 4 + 0] += p[i] * v.x;
                    o[i][jj * 4 + 1] += p[i] * v.y;
                    o[i][jj * 4 + 2] += p[i] * v.z;
                    o[i][jj * 4 + 3] += p[i] * v.w;
                }
            }
        }
    }

    #pragma unroll
    for (int i = 0; i < 4; i++) {
        float inv = 1.0f / lr[i];
        size_t rowoff = (size_t)(b * SS + qbase + r0 + i) * HD;
        #pragma unroll
        for (int jj = 0; jj < 4; jj++) {
            float4 v = make_float4(o[i][jj * 4 + 0] * inv, o[i][jj * 4 + 1] * inv,
                                   o[i][jj * 4 + 2] * inv, o[i][jj * 4 + 3] * inv);
            *(float4*)&Out[rowoff + 4 * tx + 32 * jj] = v;
        }
    }
}

// ---------------------------------------------------------------------------
extern "C" void kernel_launch(void* const* d_in, const int* in_sizes, int n_in,
                              void* d_out, int out_size) {
    const float* E  = (const float*)d_in[0];
    const float* Wk = (const float*)d_in[1];
    const float* Wq = (const float*)d_in[2];
    const float* Wv = (const float*)d_in[3];
    float* Out = (float*)d_out;

    // Split fp32 -> bf16 hi/lo
    const int n4E = NROWS * MD / 4;
    split_kernel<<<(n4E + 255) / 256, 256>>>(E, n4E, 1, 0);
    const int n4W = HD * MD / 4;
    split_kernel<<<(n4W + 255) / 256, 256>>>(Wk, n4W, 0, 0L);
    split_kernel<<<(n4W + 255) / 256, 256>>>(Wq, n4W, 0, (long)HD * MD);
    split_kernel<<<(n4W + 255) / 256, 256>>>(Wv, n4W, 0, 2L * HD * MD);

    // HMMA QKV projection
    cudaFuncSetAttribute(qkv_hmma_kernel, cudaFuncAttributeMaxDynamicSharedMemorySize, GEMM_SMEM);
    qkv_hmma_kernel<<<dim3(NROWS / 128, 3), 256, GEMM_SMEM>>>();

    // fp32 causal flash attention
    size_t smem = (size_t)SMEM_FLOATS * sizeof(float);
    cudaFuncSetAttribute(attn_kernel, cudaFuncAttributeMaxDynamicSharedMemorySize, (int)smem);
    attn_kernel<<<BB * NQT, ATT_THREADS, smem>>>(Out);
}

// round 9
// speedup vs baseline: 2.7022x; 2.3261x over previous
#include <cuda_runtime.h>
#include <cuda_bf16.h>
#include <cstdint>

// Problem constants
#define BB 4
#define SS 4096
#define MD 1024
#define HD 128
#define NROWS (BB*SS)      // 16384
#define NCOL  384

// HMMA projection GEMM tiling
#define KC 32
#define PITCHB 80
#define TILEB (128*PITCHB)
#define STAGEB (4*TILEB)
#define GEMM_SMEM (2*STAGEB)        // 81920 B

// HMMA attention tiling
#define AQT 64                      // q rows per CTA
#define AKB 64                      // keys per k-block
#define APITCH 272                  // smem row pitch bytes (128 bf16 + pad)
#define QTILE (AQT*APITCH)          // 17408
#define KVTILE (AKB*APITCH)         // 17408
#define ASTAGE (4*KVTILE)           // Khi,Klo,Vhi,Vlo = 69632
#define ATT_SMEM (2*QTILE + 2*ASTAGE)   // 174080

// Scratch (device globals; no allocations allowed)
__device__ __nv_bfloat16 g_Ehi[NROWS*MD];
__device__ __nv_bfloat16 g_Elo[NROWS*MD];
__device__ __nv_bfloat16 g_Whi[NCOL*MD];
__device__ __nv_bfloat16 g_Wlo[NCOL*MD];
__device__ __nv_bfloat16 g_Qhi[NROWS*HD];
__device__ __nv_bfloat16 g_Qlo[NROWS*HD];
__device__ __nv_bfloat16 g_Khi[NROWS*HD];
__device__ __nv_bfloat16 g_Klo[NROWS*HD];
__device__ __nv_bfloat16 g_Vhi[NROWS*HD];
__device__ __nv_bfloat16 g_Vlo[NROWS*HD];

// ---------------------------------------------------------------------------
// PTX helpers (base sm_103 target)
// ---------------------------------------------------------------------------
__device__ __forceinline__ uint32_t smem_u32(const void* p) {
    uint32_t a;
    asm("{ .reg .u64 t; cvta.to.shared.u64 t, %1; cvt.u32.u64 %0, t; }" : "=r"(a) : "l"(p));
    return a;
}
__device__ __forceinline__ void ldsm4(uint32_t& r0, uint32_t& r1, uint32_t& r2, uint32_t& r3,
                                      uint32_t addr) {
    asm volatile("ldmatrix.sync.aligned.m8n8.x4.shared.b16 {%0,%1,%2,%3}, [%4];"
                 : "=r"(r0), "=r"(r1), "=r"(r2), "=r"(r3) : "r"(addr));
}
__device__ __forceinline__ void ldsm4t(uint32_t& r0, uint32_t& r1, uint32_t& r2, uint32_t& r3,
                                       uint32_t addr) {
    asm volatile("ldmatrix.sync.aligned.m8n8.x4.trans.shared.b16 {%0,%1,%2,%3}, [%4];"
                 : "=r"(r0), "=r"(r1), "=r"(r2), "=r"(r3) : "r"(addr));
}
__device__ __forceinline__ void mma_bf16(float* c, const uint32_t* a, const uint32_t* b) {
    asm volatile(
        "mma.sync.aligned.m16n8k16.row.col.f32.bf16.bf16.f32 "
        "{%0,%1,%2,%3},{%4,%5,%6,%7},{%8,%9},{%0,%1,%2,%3};"
        : "+f"(c[0]), "+f"(c[1]), "+f"(c[2]), "+f"(c[3])
        : "r"(a[0]), "r"(a[1]), "r"(a[2]), "r"(a[3]), "r"(b[0]), "r"(b[1]));
}
__device__ __forceinline__ void cp_async16(uint32_t dst, const void* src) {
    asm volatile("cp.async.cg.shared.global [%0], [%1], 16;" :: "r"(dst), "l"(src));
}
__device__ __forceinline__ void cp_commit() { asm volatile("cp.async.commit_group;"); }
template <int N>
__device__ __forceinline__ void cp_wait() {
    asm volatile("cp.async.wait_group %0;" :: "n"(N));
}
// split fp32 pair -> packed bf16 hi pair + lo pair
__device__ __forceinline__ void packsplit(float v0, float v1, uint32_t& hi, uint32_t& lo) {
    __nv_bfloat16 h0 = __float2bfloat16(v0), h1 = __float2bfloat16(v1);
    __nv_bfloat16 l0 = __float2bfloat16(v0 - __bfloat162float(h0));
    __nv_bfloat16 l1 = __float2bfloat16(v1 - __bfloat162float(h1));
    hi = ((uint32_t)__bfloat16_as_ushort(h1) << 16) | __bfloat16_as_ushort(h0);
    lo = ((uint32_t)__bfloat16_as_ushort(l1) << 16) | __bfloat16_as_ushort(l0);
}

// ---------------------------------------------------------------------------
// Kernel 0: fp32 -> split bf16 (hi + lo)
// ---------------------------------------------------------------------------
__global__ void split_kernel(const float* __restrict__ src, int n4, int isE, long off) {
    int i = blockIdx.x * blockDim.x + threadIdx.x;
    if (i >= n4) return;
    float4 v = ((const float4*)src)[i];
    uint32_t h01, l01, h23, l23;
    packsplit(v.x, v.y, h01, l01);
    packsplit(v.z, v.w, h23, l23);
    uint32_t* H = (uint32_t*)((isE ? g_Ehi : g_Whi) + off);
    uint32_t* L = (uint32_t*)((isE ? g_Elo : g_Wlo) + off);
    H[2 * i] = h01; H[2 * i + 1] = h23;
    L[2 * i] = l01; L[2 * i + 1] = l23;
}

// ---------------------------------------------------------------------------
// Kernel 1: split-bf16 HMMA QKV projection (validated R6).
// Epilogue now writes bf16 hi/lo Q(scaled)/K/V for the HMMA attention kernel.
// ---------------------------------------------------------------------------
__global__ __launch_bounds__(256) void qkv_hmma_kernel() {
    extern __shared__ char sm_raw[];
    const uint32_t sb = smem_u32(sm_raw);

    const int tid  = threadIdx.x;
    const int warp = tid >> 5;
    const int lane = tid & 31;
    const int mbase = blockIdx.x * 128;
    const int c0    = blockIdx.y * 128;

    const int wr = (warp >> 1) * 32;
    const int wc = (warp & 1) * 64;

    const int grp  = tid >> 6;
    const int lidx = tid & 63;
    const __nv_bfloat16* gsrc = (grp == 0) ? g_Ehi : (grp == 1) ? g_Elo
                              : (grp == 2) ? g_Whi : g_Wlo;
    const int growbase = (grp < 2) ? mbase : c0;

    auto issue_chunk = [&](int stage, int k0) {
        const uint32_t tb = sb + stage * STAGEB + grp * TILEB;
        #pragma unroll
        for (int it = 0; it < 8; it++) {
            const int idx = it * 64 + lidx;
            const int row = idx >> 2;
            const int c   = idx & 3;
            cp_async16(tb + row * PITCHB + c * 16,
                       gsrc + (size_t)(growbase + row) * MD + k0 + c * 8);
        }
        cp_commit();
    };

    float acc[2][8][4];
    #pragma unroll
    for (int m = 0; m < 2; m++)
        #pragma unroll
        for (int n = 0; n < 8; n++)
            #pragma unroll
            for (int j = 0; j < 4; j++) acc[m][n][j] = 0.f;

    issue_chunk(0, 0);
    issue_chunk(1, KC);

    const uint32_t lrow16 = (uint32_t)(lane & 15);
    const uint32_t lcol16 = (uint32_t)(lane >> 4) * 16;

    const int NCHUNK = MD / KC;
    for (int chunk = 0; chunk < NCHUNK; chunk++) {
        const int stage = chunk & 1;
        cp_wait<1>();
        __syncthreads();

        const uint32_t Ah = sb + stage * STAGEB;
        const uint32_t Al = Ah + TILEB;
        const uint32_t Bh = Ah + 2 * TILEB;
        const uint32_t Bl = Ah + 3 * TILEB;

        #pragma unroll
        for (int kk = 0; kk < 2; kk++) {
            const uint32_t kb = kk * 32 + lcol16;

            uint32_t ah[2][4], al[2][4];
            #pragma unroll
            for (int m = 0; m < 2; m++) {
                const uint32_t ro = (wr + m * 16 + lrow16) * PITCHB + kb;
                ldsm4(ah[m][0], ah[m][1], ah[m][2], ah[m][3], Ah + ro);
                ldsm4(al[m][0], al[m][1], al[m][2], al[m][3], Al + ro);
            }
            uint32_t bh[8][2], bl[8][2];
            #pragma unroll
            for (int q = 0; q < 4; q++) {
                const uint32_t ro = (wc + q * 16 + lrow16) * PITCHB + kb;
                uint32_t r0, r1, r2, r3;
                ldsm4(r0, r1, r2, r3, Bh + ro);
                bh[q * 2][0] = r0; bh[q * 2][1] = r2;
                bh[q * 2 + 1][0] = r1; bh[q * 2 + 1][1] = r3;
                ldsm4(r0, r1, r2, r3, Bl + ro);
                bl[q * 2][0] = r0; bl[q * 2][1] = r2;
                bl[q * 2 + 1][0] = r1; bl[q * 2 + 1][1] = r3;
            }
            #pragma unroll
            for (int m = 0; m < 2; m++)
                #pragma unroll
                for (int n = 0; n < 8; n++) {
                    mma_bf16(acc[m][n], ah[m], bh[n]);
                    mma_bf16(acc[m][n], ah[m], bl[n]);
                    mma_bf16(acc[m][n], al[m], bh[n]);
                }
        }
        __syncthreads();
        if (chunk + 2 < NCHUNK) issue_chunk(stage, (chunk + 2) * KC);
    }

    // --- epilogue: fragment -> split bf16 global (Q scaled by 1/sqrt(HD)) ---
    __nv_bfloat16* oh = (blockIdx.y == 0) ? g_Khi : (blockIdx.y == 1) ? g_Qhi : g_Vhi;
    __nv_bfloat16* ol = (blockIdx.y == 0) ? g_Klo : (blockIdx.y == 1) ? g_Qlo : g_Vlo;
    const float sc = (blockIdx.y == 1) ? 0.08838834764831845f : 1.0f;
    const int qrow = lane >> 2;
    const int qcol = (lane & 3) * 2;
    #pragma unroll
    for (int m = 0; m < 2; m++) {
        const int r0g = mbase + wr + m * 16 + qrow;
        #pragma unroll
        for (int n = 0; n < 8; n++) {
            const int cg = wc + n * 8 + qcol;
            uint32_t h01, l01, h23, l23;
            packsplit(acc[m][n][0] * sc, acc[m][n][1] * sc, h01, l01);
            packsplit(acc[m][n][2] * sc, acc[m][n][3] * sc, h23, l23);
            *(uint32_t*)&oh[(size_t)r0g * HD + cg]       = h01;
            *(uint32_t*)&ol[(size_t)r0g * HD + cg]       = l01;
            *(uint32_t*)&oh[(size_t)(r0g + 8) * HD + cg] = h23;
            *(uint32_t*)&ol[(size_t)(r0g + 8) * HD + cg] = l23;
        }
    }
}

// ---------------------------------------------------------------------------
// Kernel 2: split-bf16 HMMA causal flash attention.
// CTA = 64 q rows; 4 warps x 16 rows. K-blocks of 64 keys, cp.async 2-stage.
// S via projection-identical frag idiom; P stays in registers (C-frag == A-frag);
// V B-frags via ldmatrix.x4.trans. All GEMMs 3-pass hi/lo split.
// ---------------------------------------------------------------------------
__global__ __launch_bounds__(128) void attn_hmma_kernel(float* __restrict__ Out) {
    extern __shared__ char sm_raw[];
    const uint32_t sb = smem_u32(sm_raw);

    const int tid  = threadIdx.x;
    const int warp = tid >> 5;
    const int lane = tid & 31;
    const int bid  = blockIdx.x;
    const int qt   = (SS / AQT - 1) - (bid >> 2);   // heavy diagonal first
    const int b    = bid & 3;
    const int qbase = qt * AQT;
    const int wr   = warp * 16;

    const size_t boff = (size_t)b * SS * HD;

    const uint32_t QHI = sb;
    const uint32_t QLO = sb + QTILE;

    // Load Q tile (hi/lo) into smem
    for (int i = tid; i < AQT * 16; i += 128) {
        const int row = i >> 4;
        const int c   = i & 15;
        *(uint4*)(sm_raw + row * APITCH + c * 16) =
            *(const uint4*)&g_Qhi[boff + (size_t)(qbase + row) * HD + c * 8];
        *(uint4*)(sm_raw + QTILE + row * APITCH + c * 16) =
            *(const uint4*)&g_Qlo[boff + (size_t)(qbase + row) * HD + c * 8];
    }

    const int nkb = qt + 1;

    auto issue_kv = [&](int kb, int stage) {
        if (kb < nkb) {
            const uint32_t base = sb + 2 * QTILE + stage * ASTAGE;
            const int krow0 = kb * AKB;
            for (int i = tid; i < 4 * AKB * 16; i += 128) {
                const int tile = i >> 10;
                const int idx  = i & 1023;
                const int row  = idx >> 4;
                const int c    = idx & 15;
                const __nv_bfloat16* g = (tile == 0) ? g_Khi : (tile == 1) ? g_Klo
                                       : (tile == 2) ? g_Vhi : g_Vlo;
                cp_async16(base + tile * KVTILE + row * APITCH + c * 16,
                           g + boff + (size_t)(krow0 + row) * HD + c * 8);
            }
        }
        cp_commit();
    };

    float of[16][4];
    #pragma unroll
    for (int n = 0; n < 16; n++)
        #pragma unroll
        for (int j = 0; j < 4; j++) of[n][j] = 0.f;
    float m0 = -1e30f, m1 = -1e30f;
    float l0 = 0.f, l1 = 0.f;

    issue_kv(0, 0);
    issue_kv(1, 1);

    const uint32_t lrow16 = (uint32_t)(lane & 15);
    const uint32_t lcol16 = (uint32_t)(lane >> 4) * 16;

    for (int kb = 0; kb < nkb; kb++) {
        const int stage = kb & 1;
        cp_wait<1>();
        __syncthreads();

        const uint32_t KHI = sb + 2 * QTILE + stage * ASTAGE;
        const uint32_t KLO = KHI + KVTILE;
        const uint32_t VHI = KHI + 2 * KVTILE;
        const uint32_t VLO = KHI + 3 * KVTILE;

        // ---- S = Qs @ Ks^T : 8 n-tiles of 64 keys, 3-pass split ----
        float sf[8][4];
        #pragma unroll
        for (int n = 0; n < 8; n++)
            #pragma unroll
            for (int j = 0; j < 4; j++) sf[n][j] = 0.f;

        #pragma unroll
        for (int ks = 0; ks < 8; ks++) {
            const uint32_t kbyte = ks * 32 + lcol16;
            uint32_t qh[4], ql[4];
            const uint32_t roq = (wr + lrow16) * APITCH + kbyte;
            ldsm4(qh[0], qh[1], qh[2], qh[3], QHI + roq);
            ldsm4(ql[0], ql[1], ql[2], ql[3], QLO + roq);
            uint32_t kh[8][2], kl[8][2];
            #pragma unroll
            for (int q = 0; q < 4; q++) {
                const uint32_t ro = (q * 16 + lrow16) * APITCH + kbyte;
                uint32_t r0, r1, r2, r3;
                ldsm4(r0, r1, r2, r3, KHI + ro);
                kh[q * 2][0] = r0; kh[q * 2][1] = r2;
                kh[q * 2 + 1][0] = r1; kh[q * 2 + 1][1] = r3;
                ldsm4(r0, r1, r2, r3, KLO + ro);
                kl[q * 2][0] = r0; kl[q * 2][1] = r2;
                kl[q * 2 + 1][0] = r1; kl[q * 2 + 1][1] = r3;
            }
            #pragma unroll
            for (int n = 0; n < 8; n++) {
                mma_bf16(sf[n], qh, kh[n]);
                mma_bf16(sf[n], qh, kl[n]);
                mma_bf16(sf[n], ql, kh[n]);
            }
        }

        // ---- causal mask (diagonal block only) + online softmax ----
        if (kb == qt) {
            const int rlo = wr + (lane >> 2);
            #pragma unroll
            for (int n = 0; n < 8; n++) {
                const int key0 = n * 8 + (lane & 3) * 2;
                if (key0 > rlo)     sf[n][0] = -1e30f;
                if (key0 + 1 > rlo) sf[n][1] = -1e30f;
                if (key0 > rlo + 8)     sf[n][2] = -1e30f;
                if (key0 + 1 > rlo + 8) sf[n][3] = -1e30f;
            }
        }
        float mx0 = sf[0][0], mx1 = sf[0][2];
        #pragma unroll
        for (int n = 0; n < 8; n++) {
            mx0 = fmaxf(mx0, fmaxf(sf[n][0], sf[n][1]));
            mx1 = fmaxf(mx1, fmaxf(sf[n][2], sf[n][3]));
        }
        mx0 = fmaxf(mx0, __shfl_xor_sync(0xffffffffu, mx0, 1));
        mx0 = fmaxf(mx0, __shfl_xor_sync(0xffffffffu, mx0, 2));
        mx1 = fmaxf(mx1, __shfl_xor_sync(0xffffffffu, mx1, 1));
        mx1 = fmaxf(mx1, __shfl_xor_sync(0xffffffffu, mx1, 2));
        const float mn0 = fmaxf(m0, mx0);
        const float mn1 = fmaxf(m1, mx1);
        const float a0 = __expf(m0 - mn0);
        const float a1 = __expf(m1 - mn1);
        m0 = mn0; m1 = mn1;
        float ls0 = 0.f, ls1 = 0.f;
        #pragma unroll
        for (int n = 0; n < 8; n++) {
            sf[n][0] = __expf(sf[n][0] - mn0); ls0 += sf[n][0];
            sf[n][1] = __expf(sf[n][1] - mn0); ls0 += sf[n][1];
            sf[n][2] = __expf(sf[n][2] - mn1); ls1 += sf[n][2];
            sf[n][3] = __expf(sf[n][3] - mn1); ls1 += sf[n][3];
        }
        ls0 += __shfl_xor_sync(0xffffffffu, ls0, 1);
        ls0 += __shfl_xor_sync(0xffffffffu, ls0, 2);
        ls1 += __shfl_xor_sync(0xffffffffu, ls1, 1);
        ls1 += __shfl_xor_sync(0xffffffffu, ls1, 2);
        l0 = l0 * a0 + ls0;
        l1 = l1 * a1 + ls1;
        #pragma unroll
        for (int n = 0; n < 16; n++) {
            of[n][0] *= a0; of[n][1] *= a0;
            of[n][2] *= a1; of[n][3] *= a1;
        }

        // ---- O += P @ V : P in registers (C-frag -> A-frag), V via ldsm.trans ----
        #pragma unroll
        for (int kk = 0; kk < 4; kk++) {
            uint32_t phi[4], plo[4];
            packsplit(sf[2 * kk][0],     sf[2 * kk][1],     phi[0], plo[0]);
            packsplit(sf[2 * kk][2],     sf[2 * kk][3],     phi[1], plo[1]);
            packsplit(sf[2 * kk + 1][0], sf[2 * kk + 1][1], phi[2], plo[2]);
            packsplit(sf[2 * kk + 1][2], sf[2 * kk + 1][3], phi[3], plo[3]);
            const uint32_t vrow = kk * 16 + (lane & 7) + ((lane >> 3) & 1) * 8;
            #pragma unroll
            for (int p = 0; p < 8; p++) {
                const uint32_t addr = vrow * APITCH + p * 32 + (lane >> 4) * 16;
                uint32_t vh0[2], vh1[2], vl0[2], vl1[2];
                uint32_t r0, r1, r2, r3;
                ldsm4t(r0, r1, r2, r3, VHI + addr);
                vh0[0] = r0; vh0[1] = r1; vh1[0] = r2; vh1[1] = r3;
                ldsm4t(r0, r1, r2, r3, VLO + addr);
                vl0[0] = r0; vl0[1] = r1; vl1[0] = r2; vl1[1] = r3;
                mma_bf16(of[2 * p],     phi, vh0);
                mma_bf16(of[2 * p],     phi, vl0);
                mma_bf16(of[2 * p],     plo, vh0);
                mma_bf16(of[2 * p + 1], phi, vh1);
                mma_bf16(of[2 * p + 1], phi, vl1);
                mma_bf16(of[2 * p + 1], plo, vh1);
            }
        }
        __syncthreads();
        issue_kv(kb + 2, stage);
    }

    // ---- epilogue: normalize, store fp32 ----
    const float i0 = 1.0f / l0;
    const float i1 = 1.0f / l1;
    const size_t row0 = (size_t)(b * SS + qbase + wr + (lane >> 2)) * HD;
    const size_t row1 = row0 + 8 * HD;
    #pragma unroll
    for (int n = 0; n < 16; n++) {
        const int col = n * 8 + (lane & 3) * 2;
        *(float2*)&Out[row0 + col] = make_float2(of[n][0] * i0, of[n][1] * i0);
        *(float2*)&Out[row1 + col] = make_float2(of[n][2] * i1, of[n][3] * i1);
    }
}

// ---------------------------------------------------------------------------
extern "C" void kernel_launch(void* const* d_in, const int* in_sizes, int n_in,
                              void* d_out, int out_size) {
    const float* E  = (const float*)d_in[0];
    const float* Wk = (const float*)d_in[1];
    const float* Wq = (const float*)d_in[2];
    const float* Wv = (const float*)d_in[3];
    float* Out = (float*)d_out;

    const int n4E = NROWS * MD / 4;
    split_kernel<<<(n4E + 255) / 256, 256>>>(E, n4E, 1, 0);
    const int n4W = HD * MD / 4;
    split_kernel<<<(n4W + 255) / 256, 256>>>(Wk, n4W, 0, 0L);
    split_kernel<<<(n4W + 255) / 256, 256>>>(Wq, n4W, 0, (long)HD * MD);
    split_kernel<<<(n4W + 255) / 256, 256>>>(Wv, n4W, 0, 2L * HD * MD);

    cudaFuncSetAttribute(qkv_hmma_kernel, cudaFuncAttributeMaxDynamicSharedMemorySize, GEMM_SMEM);
    qkv_hmma_kernel<<<dim3(NROWS / 128, 3), 256, GEMM_SMEM>>>();

    cudaFuncSetAttribute(attn_hmma_kernel, cudaFuncAttributeMaxDynamicSharedMemorySize, ATT_SMEM);
    attn_hmma_kernel<<<BB * (SS / AQT), 128, ATT_SMEM>>>(Out);
}